// round 9
// baseline (speedup 1.0000x reference)
#include <cuda_runtime.h>
#include <cuda_fp16.h>
#include <math.h>

// PaGNN: N=100000 nodes, E=1600000 edges, D=128, H=128, C=40
#define NN 100000
#define DF 128
#define NC 40

#define SCAN_CHUNK 1024
#define SCAN_NB ((NN + SCAN_CHUNK - 1) / SCAN_CHUNK)   // 98

typedef unsigned long long ull;

// ---- scratch (device globals; no runtime allocation allowed) ---------------
__device__ __half g_xmh [NN * DF];     // x * mask in fp16 (gathered array)
__device__ uint4  g_mbits[NN];         // 128-bit mask per node (ballot layout)
__device__ __half g_hinh[NN * DF];     // normalized aggregation, fp16
__device__ float  g_xw   [NN * NC];    // (h1 @ W2) * dinv[node]
__device__ int    g_rowcnt[NN];
__device__ int    g_rowptr[NN + 1];
__device__ int    g_wpos [NN];
__device__ int    g_scol [2000000];
__device__ float  g_dinv [NN];
__device__ int    g_bsum [SCAN_NB];

// ---- f32x2 helpers ----------------------------------------------------------
__device__ __forceinline__ ull pack2(float v) {
    ull r;
    unsigned u = __float_as_uint(v);
    asm("mov.b64 %0, {%1, %2};" : "=l"(r) : "r"(u), "r"(u));
    return r;
}
__device__ __forceinline__ void ffma2(ull& acc, ull a, ull b) {
    asm("fma.rn.f32x2 %0, %1, %2, %0;" : "+l"(acc) : "l"(a), "l"(b));
}
__device__ __forceinline__ void unpack2(ull v, float& lo, float& hi) {
    unsigned a, b;
    asm("mov.b64 {%0, %1}, %2;" : "=r"(a), "=r"(b) : "l"(v));
    lo = __uint_as_float(a);
    hi = __uint_as_float(b);
}

// ---------------------------------------------------------------------------
// 1) prep: xmh = fp16(x*mask) + mask bitmap; zeroes rowcnt. One warp/node.
// ---------------------------------------------------------------------------
__global__ void prep_kernel(const float* __restrict__ x,
                            const unsigned int* __restrict__ mask,
                            int n) {
    int node = (blockIdx.x * blockDim.x + threadIdx.x) >> 5;
    int lane = threadIdx.x & 31;
    if (node >= n) return;

    float4 xv = reinterpret_cast<const float4*>(x)[(size_t)node * 32 + lane];
    uint4  mv = reinterpret_cast<const uint4*>(mask)[(size_t)node * 32 + lane];

    float4 xm;
    xm.x = mv.x ? xv.x : 0.0f;
    xm.y = mv.y ? xv.y : 0.0f;
    xm.z = mv.z ? xv.z : 0.0f;
    xm.w = mv.w ? xv.w : 0.0f;

    __half2 h0 = __floats2half2_rn(xm.x, xm.y);
    __half2 h1 = __floats2half2_rn(xm.z, xm.w);
    uint2 packed;
    packed.x = *reinterpret_cast<unsigned*>(&h0);
    packed.y = *reinterpret_cast<unsigned*>(&h1);
    reinterpret_cast<uint2*>(g_xmh)[(size_t)node * 32 + lane] = packed;

    unsigned b0 = __ballot_sync(0xffffffffu, mv.x != 0u);
    unsigned b1 = __ballot_sync(0xffffffffu, mv.y != 0u);
    unsigned b2 = __ballot_sync(0xffffffffu, mv.z != 0u);
    unsigned b3 = __ballot_sync(0xffffffffu, mv.w != 0u);
    if (lane == 0) {
        g_mbits[node] = make_uint4(b0, b1, b2, b3);
        g_rowcnt[node] = 0;
    }
}

// ---------------------------------------------------------------------------
// 2) histogram of destination rows
// ---------------------------------------------------------------------------
__global__ void hist_kernel(const int* __restrict__ row, int E) {
    int e = blockIdx.x * blockDim.x + threadIdx.x;
    if (e < E) atomicAdd(&g_rowcnt[row[e]], 1);
}

// ---------------------------------------------------------------------------
// 3a) scan phase A: per-block sums
// ---------------------------------------------------------------------------
__global__ void scanA_kernel() {
    __shared__ int swarp[8];
    int tid = threadIdx.x;
    int base = blockIdx.x * SCAN_CHUNK + tid * 4;

    int s = 0;
    #pragma unroll
    for (int k = 0; k < 4; k++) {
        int i = base + k;
        if (i < NN) s += g_rowcnt[i];
    }
    #pragma unroll
    for (int o = 16; o > 0; o >>= 1)
        s += __shfl_xor_sync(0xffffffffu, s, o);
    if ((tid & 31) == 0) swarp[tid >> 5] = s;
    __syncthreads();
    if (tid < 8) {
        int v = swarp[tid];
        #pragma unroll
        for (int o = 4; o > 0; o >>= 1)
            v += __shfl_xor_sync(0xffu, v, o);
        if (tid == 0) g_bsum[blockIdx.x] = v;
    }
}

// ---------------------------------------------------------------------------
// 3b) scan phase C: block offset from g_bsum + intra-block scan
// ---------------------------------------------------------------------------
__global__ void scanC_kernel(int E) {
    __shared__ int sb[SCAN_NB];
    __shared__ int sh[256];
    int tid = threadIdx.x;
    if (tid < SCAN_NB) sb[tid] = g_bsum[tid];
    __syncthreads();

    int boff = 0;
    for (int i = 0; i < SCAN_NB; i++)
        boff += (i < blockIdx.x) ? sb[i] : 0;

    int base = blockIdx.x * SCAN_CHUNK + tid * 4;
    int c[4];
    int s = 0;
    #pragma unroll
    for (int k = 0; k < 4; k++) {
        int i = base + k;
        c[k] = (i < NN) ? g_rowcnt[i] : 0;
        s += c[k];
    }
    sh[tid] = s;
    __syncthreads();
    for (int off = 1; off < 256; off <<= 1) {
        int u = (tid >= off) ? sh[tid - off] : 0;
        __syncthreads();
        sh[tid] += u;
        __syncthreads();
    }

    int prefix = boff + sh[tid] - s;
    #pragma unroll
    for (int k = 0; k < 4; k++) {
        int i = base + k;
        if (i < NN) {
            g_rowptr[i] = prefix;
            g_wpos[i]   = prefix;
            g_dinv[i]   = rsqrtf((float)c[k] + 1.0f);
            prefix += c[k];
        }
    }
    if (blockIdx.x == 0 && tid == 0) g_rowptr[NN] = E;
}

// ---------------------------------------------------------------------------
// 4) bucket-fill CSR columns
// ---------------------------------------------------------------------------
__global__ void edges_kernel(const int* __restrict__ row,
                             const int* __restrict__ col, int E) {
    int e = blockIdx.x * blockDim.x + threadIdx.x;
    if (e >= E) return;
    int p = atomicAdd(&g_wpos[row[e]], 1);
    g_scol[p] = col[e];
}

// ---------------------------------------------------------------------------
// 5) pass-1 aggregation (gather, fp16 in, fp16 out): one warp per node
// ---------------------------------------------------------------------------
__global__ void agg1_kernel(int n) {
    int node = (blockIdx.x * blockDim.x + threadIdx.x) >> 5;
    int lane = threadIdx.x & 31;
    if (node >= n) return;

    int s = g_rowptr[node];
    int e = g_rowptr[node + 1];

    float ax = 0.f, ay = 0.f, az = 0.f, aw = 0.f;
    int   cx = 0,   cy = 0,   cz = 0,   cw = 0;

    const uint2* xm2 = reinterpret_cast<const uint2*>(g_xmh);

    int j = s;
    for (; j + 4 <= e; j += 4) {
        int c0 = g_scol[j + 0];
        int c1 = g_scol[j + 1];
        int c2 = g_scol[j + 2];
        int c3 = g_scol[j + 3];
        uint2 r0 = xm2[(size_t)c0 * 32 + lane];
        uint2 r1 = xm2[(size_t)c1 * 32 + lane];
        uint2 r2 = xm2[(size_t)c2 * 32 + lane];
        uint2 r3 = xm2[(size_t)c3 * 32 + lane];
        uint4 b0 = g_mbits[c0];
        uint4 b1 = g_mbits[c1];
        uint4 b2 = g_mbits[c2];
        uint4 b3 = g_mbits[c3];

        float2 f;
        f = __half22float2(*reinterpret_cast<__half2*>(&r0.x)); ax += f.x; ay += f.y;
        f = __half22float2(*reinterpret_cast<__half2*>(&r0.y)); az += f.x; aw += f.y;
        f = __half22float2(*reinterpret_cast<__half2*>(&r1.x)); ax += f.x; ay += f.y;
        f = __half22float2(*reinterpret_cast<__half2*>(&r1.y)); az += f.x; aw += f.y;
        f = __half22float2(*reinterpret_cast<__half2*>(&r2.x)); ax += f.x; ay += f.y;
        f = __half22float2(*reinterpret_cast<__half2*>(&r2.y)); az += f.x; aw += f.y;
        f = __half22float2(*reinterpret_cast<__half2*>(&r3.x)); ax += f.x; ay += f.y;
        f = __half22float2(*reinterpret_cast<__half2*>(&r3.y)); az += f.x; aw += f.y;

        cx += ((b0.x >> lane) & 1u) + ((b1.x >> lane) & 1u) +
              ((b2.x >> lane) & 1u) + ((b3.x >> lane) & 1u);
        cy += ((b0.y >> lane) & 1u) + ((b1.y >> lane) & 1u) +
              ((b2.y >> lane) & 1u) + ((b3.y >> lane) & 1u);
        cz += ((b0.z >> lane) & 1u) + ((b1.z >> lane) & 1u) +
              ((b2.z >> lane) & 1u) + ((b3.z >> lane) & 1u);
        cw += ((b0.w >> lane) & 1u) + ((b1.w >> lane) & 1u) +
              ((b2.w >> lane) & 1u) + ((b3.w >> lane) & 1u);
    }
    for (; j < e; j++) {
        int c = g_scol[j];
        uint2 r  = xm2[(size_t)c * 32 + lane];
        uint4 bw = g_mbits[c];
        float2 f;
        f = __half22float2(*reinterpret_cast<__half2*>(&r.x)); ax += f.x; ay += f.y;
        f = __half22float2(*reinterpret_cast<__half2*>(&r.y)); az += f.x; aw += f.y;
        cx += (bw.x >> lane) & 1u;
        cy += (bw.y >> lane) & 1u;
        cz += (bw.z >> lane) & 1u;
        cw += (bw.w >> lane) & 1u;
    }

    float hx = ax / fmaxf((float)cx, 1.0f);
    float hy = ay / fmaxf((float)cy, 1.0f);
    float hz = az / fmaxf((float)cz, 1.0f);
    float hw = aw / fmaxf((float)cw, 1.0f);

    __half2 o0 = __floats2half2_rn(hx, hy);
    __half2 o1 = __floats2half2_rn(hz, hw);
    uint2 packed;
    packed.x = *reinterpret_cast<unsigned*>(&o0);
    packed.y = *reinterpret_cast<unsigned*>(&o1);
    reinterpret_cast<uint2*>(g_hinh)[(size_t)node * 32 + lane] = packed;
}

// ---------------------------------------------------------------------------
// 6) FUSED conv1 GEMM + relu + conv2 GEMM + dinv scale.
//    256 threads, 32 nodes/block. h1 lives only in smem (never in DRAM).
//    smem: W1 64KB | W2 20KB | shHT 4KB (8-node staging) | shH1 17KB (h1 tile)
// ---------------------------------------------------------------------------
#define HP 132
__global__ __launch_bounds__(256, 2)
void gemm12_kernel(const float* __restrict__ W1,
                   const float* __restrict__ b1,
                   const float* __restrict__ W2, int n) {
    extern __shared__ float sh[];
    float* shW1 = sh;                   // [128][128]
    float* shW2 = sh + 16384;           // [128][40]
    float* shHT = sh + 16384 + 5120;    // [128][8]  transposed 8-node stage
    float* shH1 = shHT + 1024;          // [32][HP]  relu(h1) tile

    int tid = threadIdx.x;
    int j   = tid & 127;                // output column (conv1)
    int nh  = tid >> 7;                 // node half within 8-node group

    for (int i = tid; i < 128 * 128; i += 256) shW1[i] = W1[i];
    for (int i = tid; i < 128 * 40;  i += 256) shW2[i] = W2[i];
    ull bb = pack2(b1[j]);
    int base = blockIdx.x * 32;
    __syncthreads();

    // ---- conv1: 4 groups of 8 nodes ----
    for (int g = 0; g < 4; g++) {
        int nb = base + g * 8;
        {
            float t[4];
            #pragma unroll
            for (int nn = 0; nn < 4; nn++) {
                int node = nb + nh * 4 + nn;
                t[nn] = (node < n)
                    ? __half2float(g_hinh[(size_t)node * 128 + j]) : 0.0f;
            }
            reinterpret_cast<float4*>(shHT + j * 8 + nh * 4)[0] =
                make_float4(t[0], t[1], t[2], t[3]);
        }
        __syncthreads();

        ull a01 = bb, a23 = bb;
        #pragma unroll
        for (int k = 0; k < 128; k++) {
            ulonglong2 p =
                reinterpret_cast<const ulonglong2*>(shHT + k * 8 + nh * 4)[0];
            ull ww = pack2(shW1[k * 128 + j]);
            ffma2(a01, p.x, ww);
            ffma2(a23, p.y, ww);
        }

        float v[4];
        unpack2(a01, v[0], v[1]);
        unpack2(a23, v[2], v[3]);
        // write relu(h1) into the smem tile (node-major, pitch HP):
        // lanes j consecutive -> stride-1 stores, conflict-free
        #pragma unroll
        for (int nn = 0; nn < 4; nn++) {
            int srow = g * 8 + nh * 4 + nn;
            shH1[srow * HP + j] = fmaxf(v[nn], 0.0f);
        }
        __syncthreads();
    }

    // ---- conv2: 32 nodes x 10 output quads = 320 items over 256 threads ----
    for (int it = tid; it < 320; it += 256) {
        int s  = it / 10;
        int j4 = it - s * 10;
        int node = base + s;
        if (node >= n) continue;

        ull a01 = 0, a23 = 0;
        #pragma unroll
        for (int k = 0; k < 128; k++) {
            ull hh = pack2(shH1[s * HP + k]);
            ulonglong2 w =
                *reinterpret_cast<const ulonglong2*>(shW2 + k * 40 + j4 * 4);
            ffma2(a01, hh, w.x);
            ffma2(a23, hh, w.y);
        }
        float dc = g_dinv[node];
        float4 o;
        unpack2(a01, o.x, o.y);
        unpack2(a23, o.z, o.w);
        o.x *= dc; o.y *= dc; o.z *= dc; o.w *= dc;
        reinterpret_cast<float4*>(g_xw)[(size_t)node * 10 + j4] = o;
    }
}

// ---------------------------------------------------------------------------
// 7) fused GCN gather + self-loop + bias + log_softmax.
// ---------------------------------------------------------------------------
__global__ void gather2_lsm_kernel(const float* __restrict__ b2,
                                   float* __restrict__ out, int n) {
    __shared__ float shB[40];
    __shared__ float shV[320];
    __shared__ float shM[32];
    __shared__ float shL[32];
    int tid = threadIdx.x;
    if (tid < 40) shB[tid] = b2[tid];
    __syncthreads();

    int s = tid / 10;
    int p = tid - s * 10;
    int node = blockIdx.x * 32 + s;
    bool live = (node < n);

    const float4* xw4 = reinterpret_cast<const float4*>(g_xw);

    float4 o = make_float4(0.f, 0.f, 0.f, 0.f);
    if (live) {
        float dr = g_dinv[node];
        int a = g_rowptr[node];
        int b = g_rowptr[node + 1];

        float4 acc = xw4[(size_t)node * 10 + p];
        int j = a;
        for (; j + 4 <= b; j += 4) {
            int c0 = g_scol[j + 0];
            int c1 = g_scol[j + 1];
            int c2 = g_scol[j + 2];
            int c3 = g_scol[j + 3];
            float4 v0 = xw4[(size_t)c0 * 10 + p];
            float4 v1 = xw4[(size_t)c1 * 10 + p];
            float4 v2 = xw4[(size_t)c2 * 10 + p];
            float4 v3 = xw4[(size_t)c3 * 10 + p];
            acc.x += (v0.x + v1.x) + (v2.x + v3.x);
            acc.y += (v0.y + v1.y) + (v2.y + v3.y);
            acc.z += (v0.z + v1.z) + (v2.z + v3.z);
            acc.w += (v0.w + v1.w) + (v2.w + v3.w);
        }
        for (; j < b; j++) {
            int c = g_scol[j];
            float4 v = xw4[(size_t)c * 10 + p];
            acc.x += v.x; acc.y += v.y; acc.z += v.z; acc.w += v.w;
        }
        o.x = fmaf(acc.x, dr, shB[p * 4 + 0]);
        o.y = fmaf(acc.y, dr, shB[p * 4 + 1]);
        o.z = fmaf(acc.z, dr, shB[p * 4 + 2]);
        o.w = fmaf(acc.w, dr, shB[p * 4 + 3]);
    }

    shV[tid] = live ? fmaxf(fmaxf(o.x, o.y), fmaxf(o.z, o.w)) : -INFINITY;
    __syncthreads();
    if (tid < 32) {
        float m = shV[tid * 10];
        #pragma unroll
        for (int i = 1; i < 10; i++) m = fmaxf(m, shV[tid * 10 + i]);
        shM[tid] = m;
    }
    __syncthreads();

    float m = shM[s];
    float le = live ? (expf(o.x - m) + expf(o.y - m) +
                       expf(o.z - m) + expf(o.w - m)) : 0.0f;
    shV[tid] = le;
    __syncthreads();
    if (tid < 32) {
        float su = shV[tid * 10];
        #pragma unroll
        for (int i = 1; i < 10; i++) su += shV[tid * 10 + i];
        shL[tid] = logf(su);
    }
    __syncthreads();

    if (live) {
        float sub = m + shL[s];
        float4 r;
        r.x = o.x - sub; r.y = o.y - sub; r.z = o.z - sub; r.w = o.w - sub;
        reinterpret_cast<float4*>(out)[(size_t)node * 10 + p] = r;
    }
}

// ---------------------------------------------------------------------------
extern "C" void kernel_launch(void* const* d_in, const int* in_sizes, int n_in,
                              void* d_out, int out_size) {
    const float*        x    = (const float*)d_in[0];
    const unsigned int* mask = (const unsigned int*)d_in[1];
    const int*          eidx = (const int*)d_in[2];
    const float*        W1   = (const float*)d_in[3];
    const float*        b1   = (const float*)d_in[4];
    const float*        W2   = (const float*)d_in[5];
    const float*        b2   = (const float*)d_in[6];
    float* out = (float*)d_out;

    const int N = in_sizes[0] / DF;   // 100000
    const int E = in_sizes[2] / 2;    // 1600000
    const int* row = eidx;
    const int* col = eidx + E;

    prep_kernel<<<(N * 32 + 255) / 256, 256>>>(x, mask, N);
    hist_kernel<<<(E + 255) / 256, 256>>>(row, E);
    scanA_kernel<<<SCAN_NB, 256>>>();
    scanC_kernel<<<SCAN_NB, 256>>>(E);
    edges_kernel<<<(E + 255) / 256, 256>>>(row, col, E);
    agg1_kernel<<<(N + 7) / 8, 256>>>(N);

    {
        int smem = (16384 + 5120 + 1024 + 32 * HP) * (int)sizeof(float);
        cudaFuncSetAttribute(gemm12_kernel,
                             cudaFuncAttributeMaxDynamicSharedMemorySize, smem);
        gemm12_kernel<<<(N + 31) / 32, 256, smem>>>(W1, b1, W2, N);
    }

    gather2_lsm_kernel<<<(N + 31) / 32, 320>>>(b2, out, N);
}

// round 11
// speedup vs baseline: 1.4692x; 1.4692x over previous
#include <cuda_runtime.h>
#include <cuda_fp16.h>
#include <math.h>

// PaGNN: N=100000 nodes, E=1600000 edges, D=128, H=128, C=40
#define NN 100000
#define DF 128
#define NC 40

#define SCAN_CHUNK 1024
#define SCAN_NB ((NN + SCAN_CHUNK - 1) / SCAN_CHUNK)   // 98

typedef unsigned long long ull;

// ---- scratch (device globals; no runtime allocation allowed) ---------------
__device__ __half g_xmh [NN * DF];     // x * mask in fp16 (gathered array)
__device__ uint4  g_mbits[NN];         // 128-bit mask per node (ballot layout)
__device__ __half g_hinh[NN * DF];     // normalized aggregation, fp16
__device__ __half g_w1th[DF * DF];     // W1^T in fp16: w1t[j][k] = W1[k][j]
__device__ __half g_h1h [NN * DF];     // relu(conv1), fp16
__device__ float  g_xw   [NN * NC];    // (h1 @ W2) * dinv[node]
__device__ int    g_rowcnt[NN];
__device__ int    g_rowptr[NN + 1];
__device__ int    g_wpos [NN];
__device__ int    g_scol [2000000];
__device__ float  g_dinv [NN];
__device__ int    g_bsum [SCAN_NB];

// ---- f32x2 helpers ----------------------------------------------------------
__device__ __forceinline__ ull pack2(float v) {
    ull r;
    unsigned u = __float_as_uint(v);
    asm("mov.b64 %0, {%1, %2};" : "=l"(r) : "r"(u), "r"(u));
    return r;
}
__device__ __forceinline__ void ffma2(ull& acc, ull a, ull b) {
    asm("fma.rn.f32x2 %0, %1, %2, %0;" : "+l"(acc) : "l"(a), "l"(b));
}
__device__ __forceinline__ void unpack2(ull v, float& lo, float& hi) {
    unsigned a, b;
    asm("mov.b64 {%0, %1}, %2;" : "=r"(a), "=r"(b) : "l"(v));
    lo = __uint_as_float(a);
    hi = __uint_as_float(b);
}

// ---------------------------------------------------------------------------
// 0) W1 -> fp16 transposed (w1t[j][k] = W1[k][j])
// ---------------------------------------------------------------------------
__global__ void w1t_kernel(const float* __restrict__ W1) {
    int i = blockIdx.x * blockDim.x + threadIdx.x;   // 16384 threads
    int j = i >> 7;
    int k = i & 127;
    g_w1th[j * 128 + k] = __float2half(W1[k * 128 + j]);
}

// ---------------------------------------------------------------------------
// 1) prep: xmh = fp16(x*mask) + mask bitmap; zeroes rowcnt. One warp/node.
// ---------------------------------------------------------------------------
__global__ void prep_kernel(const float* __restrict__ x,
                            const unsigned int* __restrict__ mask,
                            int n) {
    int node = (blockIdx.x * blockDim.x + threadIdx.x) >> 5;
    int lane = threadIdx.x & 31;
    if (node >= n) return;

    float4 xv = reinterpret_cast<const float4*>(x)[(size_t)node * 32 + lane];
    uint4  mv = reinterpret_cast<const uint4*>(mask)[(size_t)node * 32 + lane];

    float4 xm;
    xm.x = mv.x ? xv.x : 0.0f;
    xm.y = mv.y ? xv.y : 0.0f;
    xm.z = mv.z ? xv.z : 0.0f;
    xm.w = mv.w ? xv.w : 0.0f;

    __half2 h0 = __floats2half2_rn(xm.x, xm.y);
    __half2 h1 = __floats2half2_rn(xm.z, xm.w);
    uint2 packed;
    packed.x = *reinterpret_cast<unsigned*>(&h0);
    packed.y = *reinterpret_cast<unsigned*>(&h1);
    reinterpret_cast<uint2*>(g_xmh)[(size_t)node * 32 + lane] = packed;

    unsigned b0 = __ballot_sync(0xffffffffu, mv.x != 0u);
    unsigned b1 = __ballot_sync(0xffffffffu, mv.y != 0u);
    unsigned b2 = __ballot_sync(0xffffffffu, mv.z != 0u);
    unsigned b3 = __ballot_sync(0xffffffffu, mv.w != 0u);
    if (lane == 0) {
        g_mbits[node] = make_uint4(b0, b1, b2, b3);
        g_rowcnt[node] = 0;
    }
}

// ---------------------------------------------------------------------------
// 2) histogram of destination rows
// ---------------------------------------------------------------------------
__global__ void hist_kernel(const int* __restrict__ row, int E) {
    int e = blockIdx.x * blockDim.x + threadIdx.x;
    if (e < E) atomicAdd(&g_rowcnt[row[e]], 1);
}

// ---------------------------------------------------------------------------
// 3a) scan phase A: per-block sums
// ---------------------------------------------------------------------------
__global__ void scanA_kernel() {
    __shared__ int swarp[8];
    int tid = threadIdx.x;
    int base = blockIdx.x * SCAN_CHUNK + tid * 4;

    int s = 0;
    #pragma unroll
    for (int k = 0; k < 4; k++) {
        int i = base + k;
        if (i < NN) s += g_rowcnt[i];
    }
    #pragma unroll
    for (int o = 16; o > 0; o >>= 1)
        s += __shfl_xor_sync(0xffffffffu, s, o);
    if ((tid & 31) == 0) swarp[tid >> 5] = s;
    __syncthreads();
    if (tid < 8) {
        int v = swarp[tid];
        #pragma unroll
        for (int o = 4; o > 0; o >>= 1)
            v += __shfl_xor_sync(0xffu, v, o);
        if (tid == 0) g_bsum[blockIdx.x] = v;
    }
}

// ---------------------------------------------------------------------------
// 3b) scan phase C: block offset from g_bsum + intra-block scan
// ---------------------------------------------------------------------------
__global__ void scanC_kernel(int E) {
    __shared__ int sb[SCAN_NB];
    __shared__ int sh[256];
    int tid = threadIdx.x;
    if (tid < SCAN_NB) sb[tid] = g_bsum[tid];
    __syncthreads();

    int boff = 0;
    for (int i = 0; i < SCAN_NB; i++)
        boff += (i < blockIdx.x) ? sb[i] : 0;

    int base = blockIdx.x * SCAN_CHUNK + tid * 4;
    int c[4];
    int s = 0;
    #pragma unroll
    for (int k = 0; k < 4; k++) {
        int i = base + k;
        c[k] = (i < NN) ? g_rowcnt[i] : 0;
        s += c[k];
    }
    sh[tid] = s;
    __syncthreads();
    for (int off = 1; off < 256; off <<= 1) {
        int u = (tid >= off) ? sh[tid - off] : 0;
        __syncthreads();
        sh[tid] += u;
        __syncthreads();
    }

    int prefix = boff + sh[tid] - s;
    #pragma unroll
    for (int k = 0; k < 4; k++) {
        int i = base + k;
        if (i < NN) {
            g_rowptr[i] = prefix;
            g_wpos[i]   = prefix;
            g_dinv[i]   = rsqrtf((float)c[k] + 1.0f);
            prefix += c[k];
        }
    }
    if (blockIdx.x == 0 && tid == 0) g_rowptr[NN] = E;
}

// ---------------------------------------------------------------------------
// 4) bucket-fill CSR columns
// ---------------------------------------------------------------------------
__global__ void edges_kernel(const int* __restrict__ row,
                             const int* __restrict__ col, int E) {
    int e = blockIdx.x * blockDim.x + threadIdx.x;
    if (e >= E) return;
    int p = atomicAdd(&g_wpos[row[e]], 1);
    g_scol[p] = col[e];
}

// ---------------------------------------------------------------------------
// 5) pass-1 aggregation (gather, fp16 in, fp16 out): one warp per node
// ---------------------------------------------------------------------------
__global__ void agg1_kernel(int n) {
    int node = (blockIdx.x * blockDim.x + threadIdx.x) >> 5;
    int lane = threadIdx.x & 31;
    if (node >= n) return;

    int s = g_rowptr[node];
    int e = g_rowptr[node + 1];

    float ax = 0.f, ay = 0.f, az = 0.f, aw = 0.f;
    int   cx = 0,   cy = 0,   cz = 0,   cw = 0;

    const uint2* xm2 = reinterpret_cast<const uint2*>(g_xmh);

    int j = s;
    for (; j + 4 <= e; j += 4) {
        int c0 = g_scol[j + 0];
        int c1 = g_scol[j + 1];
        int c2 = g_scol[j + 2];
        int c3 = g_scol[j + 3];
        uint2 r0 = xm2[(size_t)c0 * 32 + lane];
        uint2 r1 = xm2[(size_t)c1 * 32 + lane];
        uint2 r2 = xm2[(size_t)c2 * 32 + lane];
        uint2 r3 = xm2[(size_t)c3 * 32 + lane];
        uint4 b0 = g_mbits[c0];
        uint4 b1 = g_mbits[c1];
        uint4 b2 = g_mbits[c2];
        uint4 b3 = g_mbits[c3];

        float2 f;
        f = __half22float2(*reinterpret_cast<__half2*>(&r0.x)); ax += f.x; ay += f.y;
        f = __half22float2(*reinterpret_cast<__half2*>(&r0.y)); az += f.x; aw += f.y;
        f = __half22float2(*reinterpret_cast<__half2*>(&r1.x)); ax += f.x; ay += f.y;
        f = __half22float2(*reinterpret_cast<__half2*>(&r1.y)); az += f.x; aw += f.y;
        f = __half22float2(*reinterpret_cast<__half2*>(&r2.x)); ax += f.x; ay += f.y;
        f = __half22float2(*reinterpret_cast<__half2*>(&r2.y)); az += f.x; aw += f.y;
        f = __half22float2(*reinterpret_cast<__half2*>(&r3.x)); ax += f.x; ay += f.y;
        f = __half22float2(*reinterpret_cast<__half2*>(&r3.y)); az += f.x; aw += f.y;

        cx += ((b0.x >> lane) & 1u) + ((b1.x >> lane) & 1u) +
              ((b2.x >> lane) & 1u) + ((b3.x >> lane) & 1u);
        cy += ((b0.y >> lane) & 1u) + ((b1.y >> lane) & 1u) +
              ((b2.y >> lane) & 1u) + ((b3.y >> lane) & 1u);
        cz += ((b0.z >> lane) & 1u) + ((b1.z >> lane) & 1u) +
              ((b2.z >> lane) & 1u) + ((b3.z >> lane) & 1u);
        cw += ((b0.w >> lane) & 1u) + ((b1.w >> lane) & 1u) +
              ((b2.w >> lane) & 1u) + ((b3.w >> lane) & 1u);
    }
    for (; j < e; j++) {
        int c = g_scol[j];
        uint2 r  = xm2[(size_t)c * 32 + lane];
        uint4 bw = g_mbits[c];
        float2 f;
        f = __half22float2(*reinterpret_cast<__half2*>(&r.x)); ax += f.x; ay += f.y;
        f = __half22float2(*reinterpret_cast<__half2*>(&r.y)); az += f.x; aw += f.y;
        cx += (bw.x >> lane) & 1u;
        cy += (bw.y >> lane) & 1u;
        cz += (bw.z >> lane) & 1u;
        cw += (bw.w >> lane) & 1u;
    }

    float hx = ax / fmaxf((float)cx, 1.0f);
    float hy = ay / fmaxf((float)cy, 1.0f);
    float hz = az / fmaxf((float)cz, 1.0f);
    float hw = aw / fmaxf((float)cw, 1.0f);

    __half2 o0 = __floats2half2_rn(hx, hy);
    __half2 o1 = __floats2half2_rn(hz, hw);
    uint2 packed;
    packed.x = *reinterpret_cast<unsigned*>(&o0);
    packed.y = *reinterpret_cast<unsigned*>(&o1);
    reinterpret_cast<uint2*>(g_hinh)[(size_t)node * 32 + lane] = packed;
}

// ---------------------------------------------------------------------------
// 6) conv1 via tensor cores: h1h = relu(hinh @ W1 + b1), fp16 in, fp32 accum.
//    mma.sync.m16n8k16. 8 warps; warp w owns 16 nodes, ALL 128 output cols
//    = 16 n-tiles (FIX: was 8 tiles = only 64 cols in R10).
// ---------------------------------------------------------------------------
#define PJ 136
__global__ __launch_bounds__(256)
void gemm1_mma_kernel(const float* __restrict__ bias1, int n) {
    __shared__ __half sB[128 * PJ];    // ~34KB

    int tid  = threadIdx.x;
    int warp = tid >> 5;
    int lane = tid & 31;
    int g = lane >> 2;      // groupID 0..7
    int t = lane & 3;       // threadID_in_group 0..3

    // stage W1T (row j, col k) into padded smem
    for (int i = tid; i < 128 * 128; i += 256) {
        int j = i >> 7, k = i & 127;
        sB[j * PJ + k] = g_w1th[i];
    }
    __syncthreads();

    int nb = blockIdx.x * 128 + warp * 16;
    int row0 = nb + g;
    int row1 = nb + g + 8;
    bool v0 = row0 < n;
    bool v1 = row1 < n;

    const __half* A0 = g_hinh + (size_t)row0 * 128;
    const __half* A1 = g_hinh + (size_t)row1 * 128;

    float acc[16][4];
    #pragma unroll
    for (int i = 0; i < 16; i++) {
        acc[i][0] = 0.f; acc[i][1] = 0.f; acc[i][2] = 0.f; acc[i][3] = 0.f;
    }

    #pragma unroll
    for (int k0 = 0; k0 < 128; k0 += 16) {
        unsigned a0 = v0 ? *reinterpret_cast<const unsigned*>(A0 + k0 + 2 * t) : 0u;
        unsigned a1 = v1 ? *reinterpret_cast<const unsigned*>(A1 + k0 + 2 * t) : 0u;
        unsigned a2 = v0 ? *reinterpret_cast<const unsigned*>(A0 + k0 + 8 + 2 * t) : 0u;
        unsigned a3 = v1 ? *reinterpret_cast<const unsigned*>(A1 + k0 + 8 + 2 * t) : 0u;

        #pragma unroll
        for (int nt = 0; nt < 16; nt++) {
            const __half* Bp = sB + (nt * 8 + g) * PJ + k0;
            unsigned bb0 = *reinterpret_cast<const unsigned*>(Bp + 2 * t);
            unsigned bb1 = *reinterpret_cast<const unsigned*>(Bp + 8 + 2 * t);
            asm volatile(
                "mma.sync.aligned.m16n8k16.row.col.f32.f16.f16.f32 "
                "{%0,%1,%2,%3}, {%4,%5,%6,%7}, {%8,%9}, {%0,%1,%2,%3};"
                : "+f"(acc[nt][0]), "+f"(acc[nt][1]),
                  "+f"(acc[nt][2]), "+f"(acc[nt][3])
                : "r"(a0), "r"(a1), "r"(a2), "r"(a3), "r"(bb0), "r"(bb1));
        }
    }

    // epilogue: c0,c1 -> (row0, col 2t,2t+1); c2,c3 -> (row1, same cols)
    #pragma unroll
    for (int nt = 0; nt < 16; nt++) {
        int jc = nt * 8 + 2 * t;
        float bx = bias1[jc];
        float by = bias1[jc + 1];
        if (v0) {
            __half2 h = __floats2half2_rn(fmaxf(acc[nt][0] + bx, 0.f),
                                          fmaxf(acc[nt][1] + by, 0.f));
            *reinterpret_cast<__half2*>(g_h1h + (size_t)row0 * 128 + jc) = h;
        }
        if (v1) {
            __half2 h = __floats2half2_rn(fmaxf(acc[nt][2] + bx, 0.f),
                                          fmaxf(acc[nt][3] + by, 0.f));
            *reinterpret_cast<__half2*>(g_h1h + (size_t)row1 * 128 + jc) = h;
        }
    }
}

// ---------------------------------------------------------------------------
// 7) xw = (h1h @ W2) * dinv[node]: 640 threads, 64 nodes/block
// ---------------------------------------------------------------------------
#define HP 132
__global__ void gemm2_kernel(const float* __restrict__ W2, int n) {
    __shared__ float shW[128 * 40];
    __shared__ float shH[64 * HP];
    int tid = threadIdx.x;

    for (int i = tid; i < 128 * 40; i += 640) shW[i] = W2[i];

    int base = blockIdx.x * 64;
    for (int i = tid; i < 64 * 64; i += 640) {       // 64 nodes x 64 half2
        int s  = i >> 6;
        int kk = (i & 63) * 2;
        int node = base + s;
        float2 f = make_float2(0.f, 0.f);
        if (node < n) {
            __half2 h = *reinterpret_cast<const __half2*>(
                g_h1h + (size_t)node * 128 + kk);
            f = __half22float2(h);
        }
        shH[s * HP + kk]     = f.x;
        shH[s * HP + kk + 1] = f.y;
    }
    __syncthreads();

    int s  = tid / 10;
    int j4 = tid - s * 10;
    int node = base + s;
    if (node >= n) return;

    ull a01 = 0, a23 = 0;
    #pragma unroll
    for (int k = 0; k < 128; k++) {
        ull hh = pack2(shH[s * HP + k]);
        ulonglong2 w =
            *reinterpret_cast<const ulonglong2*>(shW + k * 40 + j4 * 4);
        ffma2(a01, hh, w.x);
        ffma2(a23, hh, w.y);
    }

    float dc = g_dinv[node];
    float4 o;
    unpack2(a01, o.x, o.y);
    unpack2(a23, o.z, o.w);
    o.x *= dc; o.y *= dc; o.z *= dc; o.w *= dc;
    reinterpret_cast<float4*>(g_xw)[(size_t)node * 10 + j4] = o;
}

// ---------------------------------------------------------------------------
// 8) fused GCN gather + self-loop + bias + log_softmax.
// ---------------------------------------------------------------------------
__global__ void gather2_lsm_kernel(const float* __restrict__ b2,
                                   float* __restrict__ out, int n) {
    __shared__ float shB[40];
    __shared__ float shV[320];
    __shared__ float shM[32];
    __shared__ float shL[32];
    int tid = threadIdx.x;
    if (tid < 40) shB[tid] = b2[tid];
    __syncthreads();

    int s = tid / 10;
    int p = tid - s * 10;
    int node = blockIdx.x * 32 + s;
    bool live = (node < n);

    const float4* xw4 = reinterpret_cast<const float4*>(g_xw);

    float4 o = make_float4(0.f, 0.f, 0.f, 0.f);
    if (live) {
        float dr = g_dinv[node];
        int a = g_rowptr[node];
        int b = g_rowptr[node + 1];

        float4 acc = xw4[(size_t)node * 10 + p];
        int j = a;
        for (; j + 4 <= b; j += 4) {
            int c0 = g_scol[j + 0];
            int c1 = g_scol[j + 1];
            int c2 = g_scol[j + 2];
            int c3 = g_scol[j + 3];
            float4 v0 = xw4[(size_t)c0 * 10 + p];
            float4 v1 = xw4[(size_t)c1 * 10 + p];
            float4 v2 = xw4[(size_t)c2 * 10 + p];
            float4 v3 = xw4[(size_t)c3 * 10 + p];
            acc.x += (v0.x + v1.x) + (v2.x + v3.x);
            acc.y += (v0.y + v1.y) + (v2.y + v3.y);
            acc.z += (v0.z + v1.z) + (v2.z + v3.z);
            acc.w += (v0.w + v1.w) + (v2.w + v3.w);
        }
        for (; j < b; j++) {
            int c = g_scol[j];
            float4 v = xw4[(size_t)c * 10 + p];
            acc.x += v.x; acc.y += v.y; acc.z += v.z; acc.w += v.w;
        }
        o.x = fmaf(acc.x, dr, shB[p * 4 + 0]);
        o.y = fmaf(acc.y, dr, shB[p * 4 + 1]);
        o.z = fmaf(acc.z, dr, shB[p * 4 + 2]);
        o.w = fmaf(acc.w, dr, shB[p * 4 + 3]);
    }

    shV[tid] = live ? fmaxf(fmaxf(o.x, o.y), fmaxf(o.z, o.w)) : -INFINITY;
    __syncthreads();
    if (tid < 32) {
        float m = shV[tid * 10];
        #pragma unroll
        for (int i = 1; i < 10; i++) m = fmaxf(m, shV[tid * 10 + i]);
        shM[tid] = m;
    }
    __syncthreads();

    float m = shM[s];
    float le = live ? (expf(o.x - m) + expf(o.y - m) +
                       expf(o.z - m) + expf(o.w - m)) : 0.0f;
    shV[tid] = le;
    __syncthreads();
    if (tid < 32) {
        float su = shV[tid * 10];
        #pragma unroll
        for (int i = 1; i < 10; i++) su += shV[tid * 10 + i];
        shL[tid] = logf(su);
    }
    __syncthreads();

    if (live) {
        float sub = m + shL[s];
        float4 r;
        r.x = o.x - sub; r.y = o.y - sub; r.z = o.z - sub; r.w = o.w - sub;
        reinterpret_cast<float4*>(out)[(size_t)node * 10 + p] = r;
    }
}

// ---------------------------------------------------------------------------
extern "C" void kernel_launch(void* const* d_in, const int* in_sizes, int n_in,
                              void* d_out, int out_size) {
    const float*        x    = (const float*)d_in[0];
    const unsigned int* mask = (const unsigned int*)d_in[1];
    const int*          eidx = (const int*)d_in[2];
    const float*        W1   = (const float*)d_in[3];
    const float*        b1   = (const float*)d_in[4];
    const float*        W2   = (const float*)d_in[5];
    const float*        b2   = (const float*)d_in[6];
    float* out = (float*)d_out;

    const int N = in_sizes[0] / DF;   // 100000
    const int E = in_sizes[2] / 2;    // 1600000
    const int* row = eidx;
    const int* col = eidx + E;

    w1t_kernel<<<64, 256>>>(W1);
    prep_kernel<<<(N * 32 + 255) / 256, 256>>>(x, mask, N);
    hist_kernel<<<(E + 255) / 256, 256>>>(row, E);
    scanA_kernel<<<SCAN_NB, 256>>>();
    scanC_kernel<<<SCAN_NB, 256>>>(E);
    edges_kernel<<<(E + 255) / 256, 256>>>(row, col, E);
    agg1_kernel<<<(N + 7) / 8, 256>>>(N);

    gemm1_mma_kernel<<<(N + 127) / 128, 256>>>(b1, N);
    gemm2_kernel<<<(N + 63) / 64, 640>>>(W2, N);
    gather2_lsm_kernel<<<(N + 31) / 32, 320>>>(b2, out, N);
}

// round 12
// speedup vs baseline: 2.1041x; 1.4321x over previous
#include <cuda_runtime.h>
#include <cuda_fp16.h>
#include <math.h>

// PaGNN: N=100000 nodes, E=1600000 edges, D=128, H=128, C=40
#define NN 100000
#define DF 128
#define NC 40

#define SCAN_CHUNK 1024
#define SCAN_NB ((NN + SCAN_CHUNK - 1) / SCAN_CHUNK)   // 98

typedef unsigned long long ull;

// ---- scratch (device globals; no runtime allocation allowed) ---------------
__device__ __half g_xmh [NN * DF];     // x * mask in fp16 (gathered array)
__device__ uint4  g_mbits[NN];         // 128-bit mask per node (ballot layout)
__device__ __half g_hinh[NN * DF];     // normalized aggregation, fp16
__device__ __half g_w1th[DF * DF];     // W1^T fp16: w1t[j][k] = W1[k][j]
__device__ __half g_w2th[NC * DF];     // W2^T fp16: w2t[j][k] = W2[k][j]
__device__ __half g_h1h [NN * DF];     // relu(conv1), fp16
__device__ __half g_xwh [NN * NC];     // (h1 @ W2) * dinv[node], fp16
__device__ int    g_rowcnt[NN];
__device__ int    g_rowptr[NN + 1];
__device__ int    g_wpos [NN];
__device__ int    g_scol [2000000];
__device__ float  g_dinv [NN];
__device__ int    g_bsum [SCAN_NB];

// ---------------------------------------------------------------------------
// 0) weights -> fp16 transposed
// ---------------------------------------------------------------------------
__global__ void w1t_kernel(const float* __restrict__ W1,
                           const float* __restrict__ W2) {
    int i = blockIdx.x * blockDim.x + threadIdx.x;   // 16384 threads
    int j = i >> 7;
    int k = i & 127;
    g_w1th[j * 128 + k] = __float2half(W1[k * 128 + j]);
    if (j < NC) g_w2th[j * 128 + k] = __float2half(W2[k * 40 + j]);
}

// ---------------------------------------------------------------------------
// 1) prep: xmh = fp16(x*mask) + mask bitmap; zeroes rowcnt. One warp/node.
// ---------------------------------------------------------------------------
__global__ void prep_kernel(const float* __restrict__ x,
                            const unsigned int* __restrict__ mask,
                            int n) {
    int node = (blockIdx.x * blockDim.x + threadIdx.x) >> 5;
    int lane = threadIdx.x & 31;
    if (node >= n) return;

    float4 xv = reinterpret_cast<const float4*>(x)[(size_t)node * 32 + lane];
    uint4  mv = reinterpret_cast<const uint4*>(mask)[(size_t)node * 32 + lane];

    float4 xm;
    xm.x = mv.x ? xv.x : 0.0f;
    xm.y = mv.y ? xv.y : 0.0f;
    xm.z = mv.z ? xv.z : 0.0f;
    xm.w = mv.w ? xv.w : 0.0f;

    __half2 h0 = __floats2half2_rn(xm.x, xm.y);
    __half2 h1 = __floats2half2_rn(xm.z, xm.w);
    uint2 packed;
    packed.x = *reinterpret_cast<unsigned*>(&h0);
    packed.y = *reinterpret_cast<unsigned*>(&h1);
    reinterpret_cast<uint2*>(g_xmh)[(size_t)node * 32 + lane] = packed;

    unsigned b0 = __ballot_sync(0xffffffffu, mv.x != 0u);
    unsigned b1 = __ballot_sync(0xffffffffu, mv.y != 0u);
    unsigned b2 = __ballot_sync(0xffffffffu, mv.z != 0u);
    unsigned b3 = __ballot_sync(0xffffffffu, mv.w != 0u);
    if (lane == 0) {
        g_mbits[node] = make_uint4(b0, b1, b2, b3);
        g_rowcnt[node] = 0;
    }
}

// ---------------------------------------------------------------------------
// 2) histogram of destination rows
// ---------------------------------------------------------------------------
__global__ void hist_kernel(const int* __restrict__ row, int E) {
    int e = blockIdx.x * blockDim.x + threadIdx.x;
    if (e < E) atomicAdd(&g_rowcnt[row[e]], 1);
}

// ---------------------------------------------------------------------------
// 3a) scan phase A: per-block sums
// ---------------------------------------------------------------------------
__global__ void scanA_kernel() {
    __shared__ int swarp[8];
    int tid = threadIdx.x;
    int base = blockIdx.x * SCAN_CHUNK + tid * 4;

    int s = 0;
    #pragma unroll
    for (int k = 0; k < 4; k++) {
        int i = base + k;
        if (i < NN) s += g_rowcnt[i];
    }
    #pragma unroll
    for (int o = 16; o > 0; o >>= 1)
        s += __shfl_xor_sync(0xffffffffu, s, o);
    if ((tid & 31) == 0) swarp[tid >> 5] = s;
    __syncthreads();
    if (tid < 8) {
        int v = swarp[tid];
        #pragma unroll
        for (int o = 4; o > 0; o >>= 1)
            v += __shfl_xor_sync(0xffu, v, o);
        if (tid == 0) g_bsum[blockIdx.x] = v;
    }
}

// ---------------------------------------------------------------------------
// 3b) scan phase C: block offset from g_bsum + intra-block scan
// ---------------------------------------------------------------------------
__global__ void scanC_kernel(int E) {
    __shared__ int sb[SCAN_NB];
    __shared__ int sh[256];
    int tid = threadIdx.x;
    if (tid < SCAN_NB) sb[tid] = g_bsum[tid];
    __syncthreads();

    int boff = 0;
    for (int i = 0; i < SCAN_NB; i++)
        boff += (i < blockIdx.x) ? sb[i] : 0;

    int base = blockIdx.x * SCAN_CHUNK + tid * 4;
    int c[4];
    int s = 0;
    #pragma unroll
    for (int k = 0; k < 4; k++) {
        int i = base + k;
        c[k] = (i < NN) ? g_rowcnt[i] : 0;
        s += c[k];
    }
    sh[tid] = s;
    __syncthreads();
    for (int off = 1; off < 256; off <<= 1) {
        int u = (tid >= off) ? sh[tid - off] : 0;
        __syncthreads();
        sh[tid] += u;
        __syncthreads();
    }

    int prefix = boff + sh[tid] - s;
    #pragma unroll
    for (int k = 0; k < 4; k++) {
        int i = base + k;
        if (i < NN) {
            g_rowptr[i] = prefix;
            g_wpos[i]   = prefix;
            g_dinv[i]   = rsqrtf((float)c[k] + 1.0f);
            prefix += c[k];
        }
    }
    if (blockIdx.x == 0 && tid == 0) g_rowptr[NN] = E;
}

// ---------------------------------------------------------------------------
// 4) bucket-fill CSR columns
// ---------------------------------------------------------------------------
__global__ void edges_kernel(const int* __restrict__ row,
                             const int* __restrict__ col, int E) {
    int e = blockIdx.x * blockDim.x + threadIdx.x;
    if (e >= E) return;
    int p = atomicAdd(&g_wpos[row[e]], 1);
    g_scol[p] = col[e];
}

// ---------------------------------------------------------------------------
// 5) pass-1 aggregation (gather, fp16 in, fp16 out): one warp per node
// ---------------------------------------------------------------------------
__global__ void agg1_kernel(int n) {
    int node = (blockIdx.x * blockDim.x + threadIdx.x) >> 5;
    int lane = threadIdx.x & 31;
    if (node >= n) return;

    int s = g_rowptr[node];
    int e = g_rowptr[node + 1];

    float ax = 0.f, ay = 0.f, az = 0.f, aw = 0.f;
    int   cx = 0,   cy = 0,   cz = 0,   cw = 0;

    const uint2* xm2 = reinterpret_cast<const uint2*>(g_xmh);

    int j = s;
    for (; j + 4 <= e; j += 4) {
        int c0 = g_scol[j + 0];
        int c1 = g_scol[j + 1];
        int c2 = g_scol[j + 2];
        int c3 = g_scol[j + 3];
        uint2 r0 = xm2[(size_t)c0 * 32 + lane];
        uint2 r1 = xm2[(size_t)c1 * 32 + lane];
        uint2 r2 = xm2[(size_t)c2 * 32 + lane];
        uint2 r3 = xm2[(size_t)c3 * 32 + lane];
        uint4 b0 = g_mbits[c0];
        uint4 b1 = g_mbits[c1];
        uint4 b2 = g_mbits[c2];
        uint4 b3 = g_mbits[c3];

        float2 f;
        f = __half22float2(*reinterpret_cast<__half2*>(&r0.x)); ax += f.x; ay += f.y;
        f = __half22float2(*reinterpret_cast<__half2*>(&r0.y)); az += f.x; aw += f.y;
        f = __half22float2(*reinterpret_cast<__half2*>(&r1.x)); ax += f.x; ay += f.y;
        f = __half22float2(*reinterpret_cast<__half2*>(&r1.y)); az += f.x; aw += f.y;
        f = __half22float2(*reinterpret_cast<__half2*>(&r2.x)); ax += f.x; ay += f.y;
        f = __half22float2(*reinterpret_cast<__half2*>(&r2.y)); az += f.x; aw += f.y;
        f = __half22float2(*reinterpret_cast<__half2*>(&r3.x)); ax += f.x; ay += f.y;
        f = __half22float2(*reinterpret_cast<__half2*>(&r3.y)); az += f.x; aw += f.y;

        cx += ((b0.x >> lane) & 1u) + ((b1.x >> lane) & 1u) +
              ((b2.x >> lane) & 1u) + ((b3.x >> lane) & 1u);
        cy += ((b0.y >> lane) & 1u) + ((b1.y >> lane) & 1u) +
              ((b2.y >> lane) & 1u) + ((b3.y >> lane) & 1u);
        cz += ((b0.z >> lane) & 1u) + ((b1.z >> lane) & 1u) +
              ((b2.z >> lane) & 1u) + ((b3.z >> lane) & 1u);
        cw += ((b0.w >> lane) & 1u) + ((b1.w >> lane) & 1u) +
              ((b2.w >> lane) & 1u) + ((b3.w >> lane) & 1u);
    }
    for (; j < e; j++) {
        int c = g_scol[j];
        uint2 r  = xm2[(size_t)c * 32 + lane];
        uint4 bw = g_mbits[c];
        float2 f;
        f = __half22float2(*reinterpret_cast<__half2*>(&r.x)); ax += f.x; ay += f.y;
        f = __half22float2(*reinterpret_cast<__half2*>(&r.y)); az += f.x; aw += f.y;
        cx += (bw.x >> lane) & 1u;
        cy += (bw.y >> lane) & 1u;
        cz += (bw.z >> lane) & 1u;
        cw += (bw.w >> lane) & 1u;
    }

    float hx = ax / fmaxf((float)cx, 1.0f);
    float hy = ay / fmaxf((float)cy, 1.0f);
    float hz = az / fmaxf((float)cz, 1.0f);
    float hw = aw / fmaxf((float)cw, 1.0f);

    __half2 o0 = __floats2half2_rn(hx, hy);
    __half2 o1 = __floats2half2_rn(hz, hw);
    uint2 packed;
    packed.x = *reinterpret_cast<unsigned*>(&o0);
    packed.y = *reinterpret_cast<unsigned*>(&o1);
    reinterpret_cast<uint2*>(g_hinh)[(size_t)node * 32 + lane] = packed;
}

// ---------------------------------------------------------------------------
// 6) conv1 via tensor cores: h1h = relu(hinh @ W1 + b1). Verified mapping.
// ---------------------------------------------------------------------------
#define PJ 136
__global__ __launch_bounds__(256)
void gemm1_mma_kernel(const float* __restrict__ bias1, int n) {
    __shared__ __half sB[128 * PJ];    // ~34KB

    int tid  = threadIdx.x;
    int warp = tid >> 5;
    int lane = tid & 31;
    int g = lane >> 2;      // groupID 0..7
    int t = lane & 3;       // threadID_in_group 0..3

    for (int i = tid; i < 128 * 128; i += 256) {
        int j = i >> 7, k = i & 127;
        sB[j * PJ + k] = g_w1th[i];
    }
    __syncthreads();

    int nb = blockIdx.x * 128 + warp * 16;
    int row0 = nb + g;
    int row1 = nb + g + 8;
    bool v0 = row0 < n;
    bool v1 = row1 < n;

    const __half* A0 = g_hinh + (size_t)row0 * 128;
    const __half* A1 = g_hinh + (size_t)row1 * 128;

    float acc[16][4];
    #pragma unroll
    for (int i = 0; i < 16; i++) {
        acc[i][0] = 0.f; acc[i][1] = 0.f; acc[i][2] = 0.f; acc[i][3] = 0.f;
    }

    #pragma unroll
    for (int k0 = 0; k0 < 128; k0 += 16) {
        unsigned a0 = v0 ? *reinterpret_cast<const unsigned*>(A0 + k0 + 2 * t) : 0u;
        unsigned a1 = v1 ? *reinterpret_cast<const unsigned*>(A1 + k0 + 2 * t) : 0u;
        unsigned a2 = v0 ? *reinterpret_cast<const unsigned*>(A0 + k0 + 8 + 2 * t) : 0u;
        unsigned a3 = v1 ? *reinterpret_cast<const unsigned*>(A1 + k0 + 8 + 2 * t) : 0u;

        #pragma unroll
        for (int nt = 0; nt < 16; nt++) {
            const __half* Bp = sB + (nt * 8 + g) * PJ + k0;
            unsigned bb0 = *reinterpret_cast<const unsigned*>(Bp + 2 * t);
            unsigned bb1 = *reinterpret_cast<const unsigned*>(Bp + 8 + 2 * t);
            asm volatile(
                "mma.sync.aligned.m16n8k16.row.col.f32.f16.f16.f32 "
                "{%0,%1,%2,%3}, {%4,%5,%6,%7}, {%8,%9}, {%0,%1,%2,%3};"
                : "+f"(acc[nt][0]), "+f"(acc[nt][1]),
                  "+f"(acc[nt][2]), "+f"(acc[nt][3])
                : "r"(a0), "r"(a1), "r"(a2), "r"(a3), "r"(bb0), "r"(bb1));
        }
    }

    #pragma unroll
    for (int nt = 0; nt < 16; nt++) {
        int jc = nt * 8 + 2 * t;
        float bx = bias1[jc];
        float by = bias1[jc + 1];
        if (v0) {
            __half2 h = __floats2half2_rn(fmaxf(acc[nt][0] + bx, 0.f),
                                          fmaxf(acc[nt][1] + by, 0.f));
            *reinterpret_cast<__half2*>(g_h1h + (size_t)row0 * 128 + jc) = h;
        }
        if (v1) {
            __half2 h = __floats2half2_rn(fmaxf(acc[nt][2] + bx, 0.f),
                                          fmaxf(acc[nt][3] + by, 0.f));
            *reinterpret_cast<__half2*>(g_h1h + (size_t)row1 * 128 + jc) = h;
        }
    }
}

// ---------------------------------------------------------------------------
// 7) conv2 via tensor cores: xwh = fp16((h1h @ W2) * dinv[node]).
//    Same fragment scheme, 5 n-tiles (40 cols).
// ---------------------------------------------------------------------------
__global__ __launch_bounds__(256)
void gemm2_mma_kernel(int n) {
    __shared__ __half sB[NC * PJ];     // 40 x 136 ~ 11KB

    int tid  = threadIdx.x;
    int warp = tid >> 5;
    int lane = tid & 31;
    int g = lane >> 2;
    int t = lane & 3;

    for (int i = tid; i < NC * 128; i += 256) {
        int j = i >> 7, k = i & 127;
        sB[j * PJ + k] = g_w2th[i];
    }
    __syncthreads();

    int nb = blockIdx.x * 128 + warp * 16;
    int row0 = nb + g;
    int row1 = nb + g + 8;
    bool v0 = row0 < n;
    bool v1 = row1 < n;

    const __half* A0 = g_h1h + (size_t)row0 * 128;
    const __half* A1 = g_h1h + (size_t)row1 * 128;

    float acc[5][4];
    #pragma unroll
    for (int i = 0; i < 5; i++) {
        acc[i][0] = 0.f; acc[i][1] = 0.f; acc[i][2] = 0.f; acc[i][3] = 0.f;
    }

    #pragma unroll
    for (int k0 = 0; k0 < 128; k0 += 16) {
        unsigned a0 = v0 ? *reinterpret_cast<const unsigned*>(A0 + k0 + 2 * t) : 0u;
        unsigned a1 = v1 ? *reinterpret_cast<const unsigned*>(A1 + k0 + 2 * t) : 0u;
        unsigned a2 = v0 ? *reinterpret_cast<const unsigned*>(A0 + k0 + 8 + 2 * t) : 0u;
        unsigned a3 = v1 ? *reinterpret_cast<const unsigned*>(A1 + k0 + 8 + 2 * t) : 0u;

        #pragma unroll
        for (int nt = 0; nt < 5; nt++) {
            const __half* Bp = sB + (nt * 8 + g) * PJ + k0;
            unsigned bb0 = *reinterpret_cast<const unsigned*>(Bp + 2 * t);
            unsigned bb1 = *reinterpret_cast<const unsigned*>(Bp + 8 + 2 * t);
            asm volatile(
                "mma.sync.aligned.m16n8k16.row.col.f32.f16.f16.f32 "
                "{%0,%1,%2,%3}, {%4,%5,%6,%7}, {%8,%9}, {%0,%1,%2,%3};"
                : "+f"(acc[nt][0]), "+f"(acc[nt][1]),
                  "+f"(acc[nt][2]), "+f"(acc[nt][3])
                : "r"(a0), "r"(a1), "r"(a2), "r"(a3), "r"(bb0), "r"(bb1));
        }
    }

    float d0 = v0 ? g_dinv[row0] : 0.f;
    float d1 = v1 ? g_dinv[row1] : 0.f;
    #pragma unroll
    for (int nt = 0; nt < 5; nt++) {
        int jc = nt * 8 + 2 * t;
        if (v0) {
            __half2 h = __floats2half2_rn(acc[nt][0] * d0, acc[nt][1] * d0);
            *reinterpret_cast<__half2*>(g_xwh + (size_t)row0 * NC + jc) = h;
        }
        if (v1) {
            __half2 h = __floats2half2_rn(acc[nt][2] * d1, acc[nt][3] * d1);
            *reinterpret_cast<__half2*>(g_xwh + (size_t)row1 * NC + jc) = h;
        }
    }
}

// ---------------------------------------------------------------------------
// 8) fused GCN gather + self-loop + bias + log_softmax, fp16 xw source.
//    320 threads, 64 nodes/block; thread = (node s = tid/5, chunk p = tid%5),
//    each chunk = 8 cols (one uint4 of halfs). fp32 accumulation.
// ---------------------------------------------------------------------------
__global__ void gather2_lsm_kernel(const float* __restrict__ b2,
                                   float* __restrict__ out, int n) {
    __shared__ float shB[40];
    __shared__ float shV[320];
    __shared__ float shM[64];
    __shared__ float shL[64];
    int tid = threadIdx.x;
    if (tid < 40) shB[tid] = b2[tid];
    __syncthreads();

    int s = tid / 5;
    int p = tid - s * 5;
    int node = blockIdx.x * 64 + s;
    bool live = (node < n);

    const uint4* xw4 = reinterpret_cast<const uint4*>(g_xwh);  // 8 halfs each
    // index: node*5 + p  (40 halfs per node = 5 uint4)

    float o[8];
    #pragma unroll
    for (int i = 0; i < 8; i++) o[i] = 0.f;

    if (live) {
        float dr = g_dinv[node];
        int a = g_rowptr[node];
        int b = g_rowptr[node + 1];

        float acc[8];
        {   // self term
            uint4 r = xw4[(size_t)node * 5 + p];
            float2 f;
            f = __half22float2(*reinterpret_cast<__half2*>(&r.x)); acc[0] = f.x; acc[1] = f.y;
            f = __half22float2(*reinterpret_cast<__half2*>(&r.y)); acc[2] = f.x; acc[3] = f.y;
            f = __half22float2(*reinterpret_cast<__half2*>(&r.z)); acc[4] = f.x; acc[5] = f.y;
            f = __half22float2(*reinterpret_cast<__half2*>(&r.w)); acc[6] = f.x; acc[7] = f.y;
        }

        int j = a;
        for (; j + 2 <= b; j += 2) {
            int c0 = g_scol[j + 0];
            int c1 = g_scol[j + 1];
            uint4 r0 = xw4[(size_t)c0 * 5 + p];
            uint4 r1 = xw4[(size_t)c1 * 5 + p];
            float2 f;
            f = __half22float2(*reinterpret_cast<__half2*>(&r0.x)); acc[0] += f.x; acc[1] += f.y;
            f = __half22float2(*reinterpret_cast<__half2*>(&r0.y)); acc[2] += f.x; acc[3] += f.y;
            f = __half22float2(*reinterpret_cast<__half2*>(&r0.z)); acc[4] += f.x; acc[5] += f.y;
            f = __half22float2(*reinterpret_cast<__half2*>(&r0.w)); acc[6] += f.x; acc[7] += f.y;
            f = __half22float2(*reinterpret_cast<__half2*>(&r1.x)); acc[0] += f.x; acc[1] += f.y;
            f = __half22float2(*reinterpret_cast<__half2*>(&r1.y)); acc[2] += f.x; acc[3] += f.y;
            f = __half22float2(*reinterpret_cast<__half2*>(&r1.z)); acc[4] += f.x; acc[5] += f.y;
            f = __half22float2(*reinterpret_cast<__half2*>(&r1.w)); acc[6] += f.x; acc[7] += f.y;
        }
        for (; j < b; j++) {
            int c = g_scol[j];
            uint4 r = xw4[(size_t)c * 5 + p];
            float2 f;
            f = __half22float2(*reinterpret_cast<__half2*>(&r.x)); acc[0] += f.x; acc[1] += f.y;
            f = __half22float2(*reinterpret_cast<__half2*>(&r.y)); acc[2] += f.x; acc[3] += f.y;
            f = __half22float2(*reinterpret_cast<__half2*>(&r.z)); acc[4] += f.x; acc[5] += f.y;
            f = __half22float2(*reinterpret_cast<__half2*>(&r.w)); acc[6] += f.x; acc[7] += f.y;
        }

        #pragma unroll
        for (int i = 0; i < 8; i++)
            o[i] = fmaf(acc[i], dr, shB[p * 8 + i]);
    }

    // row max over 40 cols (5 threads x 8)
    float mloc = -INFINITY;
    if (live) {
        #pragma unroll
        for (int i = 0; i < 8; i++) mloc = fmaxf(mloc, o[i]);
    }
    shV[tid] = mloc;
    __syncthreads();
    if (tid < 64) {
        float m = shV[tid * 5];
        #pragma unroll
        for (int i = 1; i < 5; i++) m = fmaxf(m, shV[tid * 5 + i]);
        shM[tid] = m;
    }
    __syncthreads();

    float m = shM[s];
    float le = 0.f;
    if (live) {
        #pragma unroll
        for (int i = 0; i < 8; i++) le += expf(o[i] - m);
    }
    shV[tid] = le;
    __syncthreads();
    if (tid < 64) {
        float su = shV[tid * 5];
        #pragma unroll
        for (int i = 1; i < 5; i++) su += shV[tid * 5 + i];
        shL[tid] = logf(su);
    }
    __syncthreads();

    if (live) {
        float sub = m + shL[s];
        float4 r0, r1;
        r0.x = o[0] - sub; r0.y = o[1] - sub; r0.z = o[2] - sub; r0.w = o[3] - sub;
        r1.x = o[4] - sub; r1.y = o[5] - sub; r1.z = o[6] - sub; r1.w = o[7] - sub;
        reinterpret_cast<float4*>(out)[(size_t)node * 10 + p * 2 + 0] = r0;
        reinterpret_cast<float4*>(out)[(size_t)node * 10 + p * 2 + 1] = r1;
    }
}

// ---------------------------------------------------------------------------
extern "C" void kernel_launch(void* const* d_in, const int* in_sizes, int n_in,
                              void* d_out, int out_size) {
    const float*        x    = (const float*)d_in[0];
    const unsigned int* mask = (const unsigned int*)d_in[1];
    const int*          eidx = (const int*)d_in[2];
    const float*        W1   = (const float*)d_in[3];
    const float*        b1   = (const float*)d_in[4];
    const float*        W2   = (const float*)d_in[5];
    const float*        b2   = (const float*)d_in[6];
    float* out = (float*)d_out;

    const int N = in_sizes[0] / DF;   // 100000
    const int E = in_sizes[2] / 2;    // 1600000
    const int* row = eidx;
    const int* col = eidx + E;

    w1t_kernel<<<64, 256>>>(W1, W2);
    prep_kernel<<<(N * 32 + 255) / 256, 256>>>(x, mask, N);
    hist_kernel<<<(E + 255) / 256, 256>>>(row, E);
    scanA_kernel<<<SCAN_NB, 256>>>();
    scanC_kernel<<<SCAN_NB, 256>>>(E);
    edges_kernel<<<(E + 255) / 256, 256>>>(row, col, E);
    agg1_kernel<<<(N + 7) / 8, 256>>>(N);

    gemm1_mma_kernel<<<(N + 127) / 128, 256>>>(b1, N);
    gemm2_mma_kernel<<<(N + 127) / 128, 256>>>(N);
    gather2_lsm_kernel<<<(N + 63) / 64, 320>>>(b2, out, N);
}

// round 13
// speedup vs baseline: 2.2015x; 1.0463x over previous
#include <cuda_runtime.h>
#include <cuda_fp16.h>
#include <math.h>

// PaGNN: N=100000 nodes, E=1600000 edges, D=128, H=128, C=40
#define NN 100000
#define DF 128
#define NC 40

#define SCAN_CHUNK 1024
#define SCAN_NB ((NN + SCAN_CHUNK - 1) / SCAN_CHUNK)   // 98

typedef unsigned long long ull;

// ---- scratch (device globals; no runtime allocation allowed) ---------------
__device__ __half g_xmh [NN * DF];     // x * mask in fp16 (gathered array)
__device__ uint4  g_mbits[NN];         // 128-bit mask per node (ballot layout)
__device__ __half g_hinh[NN * DF];     // normalized aggregation, fp16
__device__ __half g_w1th[DF * DF];     // W1^T fp16: w1t[j][k] = W1[k][j]
__device__ __half g_w2th[NC * DF];     // W2^T fp16: w2t[j][k] = W2[k][j]
__device__ __half g_xwh [NN * NC];     // (h1 @ W2) * dinv[node], fp16
__device__ int    g_rowcnt[NN];
__device__ int    g_rowptr[NN + 1];
__device__ int    g_wpos [NN];
__device__ int    g_scol [2000000];
__device__ float  g_dinv [NN];
__device__ int    g_bsum [SCAN_NB];

// ---------------------------------------------------------------------------
// 0) weights -> fp16 transposed
// ---------------------------------------------------------------------------
__global__ void w1t_kernel(const float* __restrict__ W1,
                           const float* __restrict__ W2) {
    int i = blockIdx.x * blockDim.x + threadIdx.x;   // 16384 threads
    int j = i >> 7;
    int k = i & 127;
    g_w1th[j * 128 + k] = __float2half(W1[k * 128 + j]);
    if (j < NC) g_w2th[j * 128 + k] = __float2half(W2[k * 40 + j]);
}

// ---------------------------------------------------------------------------
// 1) prep: xmh = fp16(x*mask) + mask bitmap; zeroes rowcnt. One warp/node.
// ---------------------------------------------------------------------------
__global__ void prep_kernel(const float* __restrict__ x,
                            const unsigned int* __restrict__ mask,
                            int n) {
    int node = (blockIdx.x * blockDim.x + threadIdx.x) >> 5;
    int lane = threadIdx.x & 31;
    if (node >= n) return;

    float4 xv = reinterpret_cast<const float4*>(x)[(size_t)node * 32 + lane];
    uint4  mv = reinterpret_cast<const uint4*>(mask)[(size_t)node * 32 + lane];

    float4 xm;
    xm.x = mv.x ? xv.x : 0.0f;
    xm.y = mv.y ? xv.y : 0.0f;
    xm.z = mv.z ? xv.z : 0.0f;
    xm.w = mv.w ? xv.w : 0.0f;

    __half2 h0 = __floats2half2_rn(xm.x, xm.y);
    __half2 h1 = __floats2half2_rn(xm.z, xm.w);
    uint2 packed;
    packed.x = *reinterpret_cast<unsigned*>(&h0);
    packed.y = *reinterpret_cast<unsigned*>(&h1);
    reinterpret_cast<uint2*>(g_xmh)[(size_t)node * 32 + lane] = packed;

    unsigned b0 = __ballot_sync(0xffffffffu, mv.x != 0u);
    unsigned b1 = __ballot_sync(0xffffffffu, mv.y != 0u);
    unsigned b2 = __ballot_sync(0xffffffffu, mv.z != 0u);
    unsigned b3 = __ballot_sync(0xffffffffu, mv.w != 0u);
    if (lane == 0) {
        g_mbits[node] = make_uint4(b0, b1, b2, b3);
        g_rowcnt[node] = 0;
    }
}

// ---------------------------------------------------------------------------
// 2) histogram of destination rows
// ---------------------------------------------------------------------------
__global__ void hist_kernel(const int* __restrict__ row, int E) {
    int e = blockIdx.x * blockDim.x + threadIdx.x;
    if (e < E) atomicAdd(&g_rowcnt[row[e]], 1);
}

// ---------------------------------------------------------------------------
// 3a) scan phase A: per-block sums
// ---------------------------------------------------------------------------
__global__ void scanA_kernel() {
    __shared__ int swarp[8];
    int tid = threadIdx.x;
    int base = blockIdx.x * SCAN_CHUNK + tid * 4;

    int s = 0;
    #pragma unroll
    for (int k = 0; k < 4; k++) {
        int i = base + k;
        if (i < NN) s += g_rowcnt[i];
    }
    #pragma unroll
    for (int o = 16; o > 0; o >>= 1)
        s += __shfl_xor_sync(0xffffffffu, s, o);
    if ((tid & 31) == 0) swarp[tid >> 5] = s;
    __syncthreads();
    if (tid < 8) {
        int v = swarp[tid];
        #pragma unroll
        for (int o = 4; o > 0; o >>= 1)
            v += __shfl_xor_sync(0xffu, v, o);
        if (tid == 0) g_bsum[blockIdx.x] = v;
    }
}

// ---------------------------------------------------------------------------
// 3b) scan phase C: block offset from g_bsum + intra-block scan
// ---------------------------------------------------------------------------
__global__ void scanC_kernel(int E) {
    __shared__ int sb[SCAN_NB];
    __shared__ int sh[256];
    int tid = threadIdx.x;
    if (tid < SCAN_NB) sb[tid] = g_bsum[tid];
    __syncthreads();

    int boff = 0;
    for (int i = 0; i < SCAN_NB; i++)
        boff += (i < blockIdx.x) ? sb[i] : 0;

    int base = blockIdx.x * SCAN_CHUNK + tid * 4;
    int c[4];
    int s = 0;
    #pragma unroll
    for (int k = 0; k < 4; k++) {
        int i = base + k;
        c[k] = (i < NN) ? g_rowcnt[i] : 0;
        s += c[k];
    }
    sh[tid] = s;
    __syncthreads();
    for (int off = 1; off < 256; off <<= 1) {
        int u = (tid >= off) ? sh[tid - off] : 0;
        __syncthreads();
        sh[tid] += u;
        __syncthreads();
    }

    int prefix = boff + sh[tid] - s;
    #pragma unroll
    for (int k = 0; k < 4; k++) {
        int i = base + k;
        if (i < NN) {
            g_rowptr[i] = prefix;
            g_wpos[i]   = prefix;
            g_dinv[i]   = rsqrtf((float)c[k] + 1.0f);
            prefix += c[k];
        }
    }
    if (blockIdx.x == 0 && tid == 0) g_rowptr[NN] = E;
}

// ---------------------------------------------------------------------------
// 4) bucket-fill CSR columns
// ---------------------------------------------------------------------------
__global__ void edges_kernel(const int* __restrict__ row,
                             const int* __restrict__ col, int E) {
    int e = blockIdx.x * blockDim.x + threadIdx.x;
    if (e >= E) return;
    int p = atomicAdd(&g_wpos[row[e]], 1);
    g_scol[p] = col[e];
}

// ---------------------------------------------------------------------------
// 5) pass-1 aggregation (gather, fp16 in, fp16 out): one warp per node
// ---------------------------------------------------------------------------
__global__ void agg1_kernel(int n) {
    int node = (blockIdx.x * blockDim.x + threadIdx.x) >> 5;
    int lane = threadIdx.x & 31;
    if (node >= n) return;

    int s = g_rowptr[node];
    int e = g_rowptr[node + 1];

    float ax = 0.f, ay = 0.f, az = 0.f, aw = 0.f;
    int   cx = 0,   cy = 0,   cz = 0,   cw = 0;

    const uint2* xm2 = reinterpret_cast<const uint2*>(g_xmh);

    int j = s;
    for (; j + 4 <= e; j += 4) {
        int c0 = g_scol[j + 0];
        int c1 = g_scol[j + 1];
        int c2 = g_scol[j + 2];
        int c3 = g_scol[j + 3];
        uint2 r0 = xm2[(size_t)c0 * 32 + lane];
        uint2 r1 = xm2[(size_t)c1 * 32 + lane];
        uint2 r2 = xm2[(size_t)c2 * 32 + lane];
        uint2 r3 = xm2[(size_t)c3 * 32 + lane];
        uint4 b0 = g_mbits[c0];
        uint4 b1 = g_mbits[c1];
        uint4 b2 = g_mbits[c2];
        uint4 b3 = g_mbits[c3];

        float2 f;
        f = __half22float2(*reinterpret_cast<__half2*>(&r0.x)); ax += f.x; ay += f.y;
        f = __half22float2(*reinterpret_cast<__half2*>(&r0.y)); az += f.x; aw += f.y;
        f = __half22float2(*reinterpret_cast<__half2*>(&r1.x)); ax += f.x; ay += f.y;
        f = __half22float2(*reinterpret_cast<__half2*>(&r1.y)); az += f.x; aw += f.y;
        f = __half22float2(*reinterpret_cast<__half2*>(&r2.x)); ax += f.x; ay += f.y;
        f = __half22float2(*reinterpret_cast<__half2*>(&r2.y)); az += f.x; aw += f.y;
        f = __half22float2(*reinterpret_cast<__half2*>(&r3.x)); ax += f.x; ay += f.y;
        f = __half22float2(*reinterpret_cast<__half2*>(&r3.y)); az += f.x; aw += f.y;

        cx += ((b0.x >> lane) & 1u) + ((b1.x >> lane) & 1u) +
              ((b2.x >> lane) & 1u) + ((b3.x >> lane) & 1u);
        cy += ((b0.y >> lane) & 1u) + ((b1.y >> lane) & 1u) +
              ((b2.y >> lane) & 1u) + ((b3.y >> lane) & 1u);
        cz += ((b0.z >> lane) & 1u) + ((b1.z >> lane) & 1u) +
              ((b2.z >> lane) & 1u) + ((b3.z >> lane) & 1u);
        cw += ((b0.w >> lane) & 1u) + ((b1.w >> lane) & 1u) +
              ((b2.w >> lane) & 1u) + ((b3.w >> lane) & 1u);
    }
    for (; j < e; j++) {
        int c = g_scol[j];
        uint2 r  = xm2[(size_t)c * 32 + lane];
        uint4 bw = g_mbits[c];
        float2 f;
        f = __half22float2(*reinterpret_cast<__half2*>(&r.x)); ax += f.x; ay += f.y;
        f = __half22float2(*reinterpret_cast<__half2*>(&r.y)); az += f.x; aw += f.y;
        cx += (bw.x >> lane) & 1u;
        cy += (bw.y >> lane) & 1u;
        cz += (bw.z >> lane) & 1u;
        cw += (bw.w >> lane) & 1u;
    }

    float hx = ax / fmaxf((float)cx, 1.0f);
    float hy = ay / fmaxf((float)cy, 1.0f);
    float hz = az / fmaxf((float)cz, 1.0f);
    float hw = aw / fmaxf((float)cw, 1.0f);

    __half2 o0 = __floats2half2_rn(hx, hy);
    __half2 o1 = __floats2half2_rn(hz, hw);
    uint2 packed;
    packed.x = *reinterpret_cast<unsigned*>(&o0);
    packed.y = *reinterpret_cast<unsigned*>(&o1);
    reinterpret_cast<uint2*>(g_hinh)[(size_t)node * 32 + lane] = packed;
}

// ---------------------------------------------------------------------------
// 6) FUSED conv1 + relu + conv2, all in mma fragments.
//    Conv1's C-fragment layout (c0,c1 @ row g / c2,c3 @ row g+8, cols nt*8+2t)
//    IS conv2's A-fragment layout for k-block kb (tiles 2kb, 2kb+1) — so h1
//    never leaves registers. Writes xwh = fp16((relu(hin@W1+b1)@W2)*dinv).
// ---------------------------------------------------------------------------
#define PJ 136
__global__ __launch_bounds__(256, 2)
void gemm12_mma_kernel(const float* __restrict__ bias1, int n) {
    __shared__ __half sB1[128 * PJ];   // ~34KB
    __shared__ __half sB2[NC * PJ];    // ~11KB

    int tid  = threadIdx.x;
    int warp = tid >> 5;
    int lane = tid & 31;
    int g = lane >> 2;      // groupID 0..7
    int t = lane & 3;       // threadID_in_group 0..3

    for (int i = tid; i < 128 * 128; i += 256) {
        int j = i >> 7, k = i & 127;
        sB1[j * PJ + k] = g_w1th[i];
    }
    for (int i = tid; i < NC * 128; i += 256) {
        int j = i >> 7, k = i & 127;
        sB2[j * PJ + k] = g_w2th[i];
    }
    __syncthreads();

    int nb = blockIdx.x * 128 + warp * 16;
    int row0 = nb + g;
    int row1 = nb + g + 8;
    bool v0 = row0 < n;
    bool v1 = row1 < n;

    const __half* A0 = g_hinh + (size_t)row0 * 128;
    const __half* A1 = g_hinh + (size_t)row1 * 128;

    // ---- conv1 ----
    float acc[16][4];
    #pragma unroll
    for (int i = 0; i < 16; i++) {
        acc[i][0] = 0.f; acc[i][1] = 0.f; acc[i][2] = 0.f; acc[i][3] = 0.f;
    }

    #pragma unroll
    for (int k0 = 0; k0 < 128; k0 += 16) {
        unsigned a0 = v0 ? *reinterpret_cast<const unsigned*>(A0 + k0 + 2 * t) : 0u;
        unsigned a1 = v1 ? *reinterpret_cast<const unsigned*>(A1 + k0 + 2 * t) : 0u;
        unsigned a2 = v0 ? *reinterpret_cast<const unsigned*>(A0 + k0 + 8 + 2 * t) : 0u;
        unsigned a3 = v1 ? *reinterpret_cast<const unsigned*>(A1 + k0 + 8 + 2 * t) : 0u;

        #pragma unroll
        for (int nt = 0; nt < 16; nt++) {
            const __half* Bp = sB1 + (nt * 8 + g) * PJ + k0;
            unsigned bb0 = *reinterpret_cast<const unsigned*>(Bp + 2 * t);
            unsigned bb1 = *reinterpret_cast<const unsigned*>(Bp + 8 + 2 * t);
            asm volatile(
                "mma.sync.aligned.m16n8k16.row.col.f32.f16.f16.f32 "
                "{%0,%1,%2,%3}, {%4,%5,%6,%7}, {%8,%9}, {%0,%1,%2,%3};"
                : "+f"(acc[nt][0]), "+f"(acc[nt][1]),
                  "+f"(acc[nt][2]), "+f"(acc[nt][3])
                : "r"(a0), "r"(a1), "r"(a2), "r"(a3), "r"(bb0), "r"(bb1));
        }
    }

    // ---- bias + relu -> fp16 A-fragments for conv2 (in place) ----
    unsigned hf0[16], hf1[16];   // row g / row g+8 fragments per conv1 tile
    #pragma unroll
    for (int nt = 0; nt < 16; nt++) {
        int jc = nt * 8 + 2 * t;
        float bx = bias1[jc];
        float by = bias1[jc + 1];
        __half2 h0 = __floats2half2_rn(fmaxf(acc[nt][0] + bx, 0.f),
                                       fmaxf(acc[nt][1] + by, 0.f));
        __half2 h1 = __floats2half2_rn(fmaxf(acc[nt][2] + bx, 0.f),
                                       fmaxf(acc[nt][3] + by, 0.f));
        hf0[nt] = *reinterpret_cast<unsigned*>(&h0);
        hf1[nt] = *reinterpret_cast<unsigned*>(&h1);
    }

    // ---- conv2: A = h1 fragments, B = W2T ----
    float acc2[5][4];
    #pragma unroll
    for (int i = 0; i < 5; i++) {
        acc2[i][0] = 0.f; acc2[i][1] = 0.f; acc2[i][2] = 0.f; acc2[i][3] = 0.f;
    }

    #pragma unroll
    for (int kb = 0; kb < 8; kb++) {
        unsigned a0 = hf0[2 * kb];
        unsigned a1 = hf1[2 * kb];
        unsigned a2 = hf0[2 * kb + 1];
        unsigned a3 = hf1[2 * kb + 1];
        int k0 = kb * 16;

        #pragma unroll
        for (int nt = 0; nt < 5; nt++) {
            const __half* Bp = sB2 + (nt * 8 + g) * PJ + k0;
            unsigned bb0 = *reinterpret_cast<const unsigned*>(Bp + 2 * t);
            unsigned bb1 = *reinterpret_cast<const unsigned*>(Bp + 8 + 2 * t);
            asm volatile(
                "mma.sync.aligned.m16n8k16.row.col.f32.f16.f16.f32 "
                "{%0,%1,%2,%3}, {%4,%5,%6,%7}, {%8,%9}, {%0,%1,%2,%3};"
                : "+f"(acc2[nt][0]), "+f"(acc2[nt][1]),
                  "+f"(acc2[nt][2]), "+f"(acc2[nt][3])
                : "r"(a0), "r"(a1), "r"(a2), "r"(a3), "r"(bb0), "r"(bb1));
        }
    }

    float d0 = v0 ? g_dinv[row0] : 0.f;
    float d1 = v1 ? g_dinv[row1] : 0.f;
    #pragma unroll
    for (int nt = 0; nt < 5; nt++) {
        int jc = nt * 8 + 2 * t;
        if (v0) {
            __half2 h = __floats2half2_rn(acc2[nt][0] * d0, acc2[nt][1] * d0);
            *reinterpret_cast<__half2*>(g_xwh + (size_t)row0 * NC + jc) = h;
        }
        if (v1) {
            __half2 h = __floats2half2_rn(acc2[nt][2] * d1, acc2[nt][3] * d1);
            *reinterpret_cast<__half2*>(g_xwh + (size_t)row1 * NC + jc) = h;
        }
    }
}

// ---------------------------------------------------------------------------
// 7) fused GCN gather + self-loop + bias + log_softmax, fp16 xw source.
//    320 threads, 64 nodes/block; thread = (node s = tid/5, chunk p = tid%5).
// ---------------------------------------------------------------------------
__global__ void gather2_lsm_kernel(const float* __restrict__ b2,
                                   float* __restrict__ out, int n) {
    __shared__ float shB[40];
    __shared__ float shV[320];
    __shared__ float shM[64];
    __shared__ float shL[64];
    int tid = threadIdx.x;
    if (tid < 40) shB[tid] = b2[tid];
    __syncthreads();

    int s = tid / 5;
    int p = tid - s * 5;
    int node = blockIdx.x * 64 + s;
    bool live = (node < n);

    const uint4* xw4 = reinterpret_cast<const uint4*>(g_xwh);  // 8 halfs each

    float o[8];
    #pragma unroll
    for (int i = 0; i < 8; i++) o[i] = 0.f;

    if (live) {
        float dr = g_dinv[node];
        int a = g_rowptr[node];
        int b = g_rowptr[node + 1];

        float acc[8];
        {   // self term
            uint4 r = xw4[(size_t)node * 5 + p];
            float2 f;
            f = __half22float2(*reinterpret_cast<__half2*>(&r.x)); acc[0] = f.x; acc[1] = f.y;
            f = __half22float2(*reinterpret_cast<__half2*>(&r.y)); acc[2] = f.x; acc[3] = f.y;
            f = __half22float2(*reinterpret_cast<__half2*>(&r.z)); acc[4] = f.x; acc[5] = f.y;
            f = __half22float2(*reinterpret_cast<__half2*>(&r.w)); acc[6] = f.x; acc[7] = f.y;
        }

        int j = a;
        for (; j + 2 <= b; j += 2) {
            int c0 = g_scol[j + 0];
            int c1 = g_scol[j + 1];
            uint4 r0 = xw4[(size_t)c0 * 5 + p];
            uint4 r1 = xw4[(size_t)c1 * 5 + p];
            float2 f;
            f = __half22float2(*reinterpret_cast<__half2*>(&r0.x)); acc[0] += f.x; acc[1] += f.y;
            f = __half22float2(*reinterpret_cast<__half2*>(&r0.y)); acc[2] += f.x; acc[3] += f.y;
            f = __half22float2(*reinterpret_cast<__half2*>(&r0.z)); acc[4] += f.x; acc[5] += f.y;
            f = __half22float2(*reinterpret_cast<__half2*>(&r0.w)); acc[6] += f.x; acc[7] += f.y;
            f = __half22float2(*reinterpret_cast<__half2*>(&r1.x)); acc[0] += f.x; acc[1] += f.y;
            f = __half22float2(*reinterpret_cast<__half2*>(&r1.y)); acc[2] += f.x; acc[3] += f.y;
            f = __half22float2(*reinterpret_cast<__half2*>(&r1.z)); acc[4] += f.x; acc[5] += f.y;
            f = __half22float2(*reinterpret_cast<__half2*>(&r1.w)); acc[6] += f.x; acc[7] += f.y;
        }
        for (; j < b; j++) {
            int c = g_scol[j];
            uint4 r = xw4[(size_t)c * 5 + p];
            float2 f;
            f = __half22float2(*reinterpret_cast<__half2*>(&r.x)); acc[0] += f.x; acc[1] += f.y;
            f = __half22float2(*reinterpret_cast<__half2*>(&r.y)); acc[2] += f.x; acc[3] += f.y;
            f = __half22float2(*reinterpret_cast<__half2*>(&r.z)); acc[4] += f.x; acc[5] += f.y;
            f = __half22float2(*reinterpret_cast<__half2*>(&r.w)); acc[6] += f.x; acc[7] += f.y;
        }

        #pragma unroll
        for (int i = 0; i < 8; i++)
            o[i] = fmaf(acc[i], dr, shB[p * 8 + i]);
    }

    float mloc = -INFINITY;
    if (live) {
        #pragma unroll
        for (int i = 0; i < 8; i++) mloc = fmaxf(mloc, o[i]);
    }
    shV[tid] = mloc;
    __syncthreads();
    if (tid < 64) {
        float m = shV[tid * 5];
        #pragma unroll
        for (int i = 1; i < 5; i++) m = fmaxf(m, shV[tid * 5 + i]);
        shM[tid] = m;
    }
    __syncthreads();

    float m = shM[s];
    float le = 0.f;
    if (live) {
        #pragma unroll
        for (int i = 0; i < 8; i++) le += __expf(o[i] - m);
    }
    shV[tid] = le;
    __syncthreads();
    if (tid < 64) {
        float su = shV[tid * 5];
        #pragma unroll
        for (int i = 1; i < 5; i++) su += shV[tid * 5 + i];
        shL[tid] = __logf(su);
    }
    __syncthreads();

    if (live) {
        float sub = m + shL[s];
        float4 r0, r1;
        r0.x = o[0] - sub; r0.y = o[1] - sub; r0.z = o[2] - sub; r0.w = o[3] - sub;
        r1.x = o[4] - sub; r1.y = o[5] - sub; r1.z = o[6] - sub; r1.w = o[7] - sub;
        reinterpret_cast<float4*>(out)[(size_t)node * 10 + p * 2 + 0] = r0;
        reinterpret_cast<float4*>(out)[(size_t)node * 10 + p * 2 + 1] = r1;
    }
}

// ---------------------------------------------------------------------------
extern "C" void kernel_launch(void* const* d_in, const int* in_sizes, int n_in,
                              void* d_out, int out_size) {
    const float*        x    = (const float*)d_in[0];
    const unsigned int* mask = (const unsigned int*)d_in[1];
    const int*          eidx = (const int*)d_in[2];
    const float*        W1   = (const float*)d_in[3];
    const float*        b1   = (const float*)d_in[4];
    const float*        W2   = (const float*)d_in[5];
    const float*        b2   = (const float*)d_in[6];
    float* out = (float*)d_out;

    const int N = in_sizes[0] / DF;   // 100000
    const int E = in_sizes[2] / 2;    // 1600000
    const int* row = eidx;
    const int* col = eidx + E;

    w1t_kernel<<<64, 256>>>(W1, W2);
    prep_kernel<<<(N * 32 + 255) / 256, 256>>>(x, mask, N);
    hist_kernel<<<(E + 255) / 256, 256>>>(row, E);
    scanA_kernel<<<SCAN_NB, 256>>>();
    scanC_kernel<<<SCAN_NB, 256>>>(E);
    edges_kernel<<<(E + 255) / 256, 256>>>(row, col, E);
    agg1_kernel<<<(N + 7) / 8, 256>>>(N);

    gemm12_mma_kernel<<<(N + 127) / 128, 256>>>(b1, N);
    gather2_lsm_kernel<<<(N + 63) / 64, 320>>>(b2, out, N);
}